// round 1
// baseline (speedup 1.0000x reference)
#include <cuda_runtime.h>

#define D     448
#define MTOT  32768     // 8 * 4096
#define BM    128
#define BN    64
#define BK    16

// Scratch for the precomputed effective weight (allocation-free per harness rules).
__device__ float g_Weff[D * D];

// ---------------------------------------------------------------------------
// Kernel 1: W_eff[i][o] = sum_d (Wq[i][d]*a[d] + Wk[i][d]*b[d] + Wv[i][d]*c[d]) * Wo[d][o]
// where a[d] = SSM_A[d][d] etc.  448x448x448, trivial cost.
// grid (28, 28), block (16, 16)
// ---------------------------------------------------------------------------
__global__ void build_weff_kernel(const float* __restrict__ Wq,
                                  const float* __restrict__ Wk,
                                  const float* __restrict__ Wv,
                                  const float* __restrict__ Wo,
                                  const float* __restrict__ A,
                                  const float* __restrict__ Bm,
                                  const float* __restrict__ C) {
    __shared__ float Ms[16][17];
    __shared__ float Ws[16][17];
    const int ty = threadIdx.y, tx = threadIdx.x;
    const int row = blockIdx.y * 16 + ty;
    const int col = blockIdx.x * 16 + tx;
    float acc = 0.f;
    for (int kt = 0; kt < D; kt += 16) {
        const int k = kt + tx;
        const float a = A[k * D + k];
        const float b = Bm[k * D + k];
        const float c = C[k * D + k];
        Ms[ty][tx] = Wq[row * D + k] * a + Wk[row * D + k] * b + Wv[row * D + k] * c;
        Ws[ty][tx] = Wo[(kt + ty) * D + col];
        __syncthreads();
#pragma unroll
        for (int kk = 0; kk < 16; kk++)
            acc += Ms[ty][kk] * Ws[kk][tx];
        __syncthreads();
    }
    g_Weff[row * D + col] = acc;
}

// ---------------------------------------------------------------------------
// Kernel 2: out[m][n] = sum_k x[m][k] * W_eff[k][n]
// M = 32768, N = 448, K = 448.  BM=128, BN=64, BK=16, 256 threads,
// 8x4 outputs per thread. All dims divide evenly -> no bounds checks.
// grid (448/64 = 7, 32768/128 = 256), block 256
// ---------------------------------------------------------------------------
__global__ void __launch_bounds__(256) gemm_main_kernel(const float* __restrict__ x,
                                                        float* __restrict__ out) {
    __shared__ float As[BK][BM + 4];   // stride 132 floats: 16B-aligned rows, reduced STS conflicts
    __shared__ float Bs[BK][BN + 4];   // stride 68 floats

    const int tid = threadIdx.x;
    const int m0  = blockIdx.y * BM;
    const int n0  = blockIdx.x * BN;
    const int tx  = tid & 15;   // n-dim: 16 threads * 4 cols = 64
    const int ty  = tid >> 4;   // m-dim: 16 threads * 8 rows = 128

    float acc[8][4] = {};

    for (int kt = 0; kt < D; kt += BK) {
        // --- load A tile (128 x 16) transposed into As[k][m]: 512 float4s, 2 per thread
#pragma unroll
        for (int h = 0; h < 2; h++) {
            const int f   = tid + h * 256;
            const int row = f >> 2;          // 0..127
            const int kp  = (f & 3) * 4;     // 0,4,8,12
            const float4 v = *reinterpret_cast<const float4*>(
                &x[(size_t)(m0 + row) * D + kt + kp]);
            As[kp + 0][row] = v.x;
            As[kp + 1][row] = v.y;
            As[kp + 2][row] = v.z;
            As[kp + 3][row] = v.w;
        }
        // --- load B tile (16 x 64): 256 float4s, 1 per thread
        {
            const int row = tid >> 4;            // 0..15
            const int cp  = (tid & 15) * 4;      // 0..60
            const float4 v = *reinterpret_cast<const float4*>(
                &g_Weff[(size_t)(kt + row) * D + n0 + cp]);
            *reinterpret_cast<float4*>(&Bs[row][cp]) = v;
        }
        __syncthreads();

#pragma unroll
        for (int k = 0; k < BK; k++) {
            float a[8], b[4];
            *reinterpret_cast<float4*>(a)     = *reinterpret_cast<const float4*>(&As[k][ty * 8]);
            *reinterpret_cast<float4*>(a + 4) = *reinterpret_cast<const float4*>(&As[k][ty * 8 + 4]);
            *reinterpret_cast<float4*>(b)     = *reinterpret_cast<const float4*>(&Bs[k][tx * 4]);
#pragma unroll
            for (int i = 0; i < 8; i++)
#pragma unroll
                for (int j = 0; j < 4; j++)
                    acc[i][j] += a[i] * b[j];
        }
        __syncthreads();
    }

    // --- store 8 rows x 4 cols per thread, vectorized
#pragma unroll
    for (int i = 0; i < 8; i++) {
        const int m = m0 + ty * 8 + i;
        float4 v;
        v.x = acc[i][0]; v.y = acc[i][1]; v.z = acc[i][2]; v.w = acc[i][3];
        *reinterpret_cast<float4*>(&out[(size_t)m * D + n0 + tx * 4]) = v;
    }
}

// ---------------------------------------------------------------------------
extern "C" void kernel_launch(void* const* d_in, const int* in_sizes, int n_in,
                              void* d_out, int out_size) {
    const float* x  = (const float*)d_in[0];
    const float* Wq = (const float*)d_in[1];
    const float* Wk = (const float*)d_in[2];
    const float* Wv = (const float*)d_in[3];
    const float* Wo = (const float*)d_in[4];
    const float* A  = (const float*)d_in[5];
    const float* B  = (const float*)d_in[6];
    const float* C  = (const float*)d_in[7];

    build_weff_kernel<<<dim3(D / 16, D / 16), dim3(16, 16)>>>(Wq, Wk, Wv, Wo, A, B, C);
    gemm_main_kernel<<<dim3(D / BN, MTOT / BM), 256>>>(x, (float*)d_out);
}

// round 3
// speedup vs baseline: 2.2250x; 2.2250x over previous
#include <cuda_runtime.h>
#include <cstdint>

#define D_DIM  448
#define MTOT   32768
#define BM     128
#define BN     112
#define BK     32
#define NSTG   3
#define A_STRIDE 36                       // floats per smem row (32 + 4 pad)
#define AS_F   (BM * A_STRIDE)            // 4608 floats
#define BS_F   (BN * A_STRIDE)            // 4032 floats
#define STG_F  (AS_F + BS_F)              // 8640 floats per stage
#define SMEM_BYTES (NSTG * STG_F * 4)     // 103680

// W_eff, transposed [n][k], tf32-rounded fp32 values
__device__ __align__(16) float g_W[D_DIM * D_DIM];

// ---- helpers ----------------------------------------------------------------
__device__ __forceinline__ uint32_t smem_u32(const void* p) {
    uint32_t a;
    asm("{ .reg .u64 t; cvta.to.shared.u64 t, %1; cvt.u32.u64 %0, t; }" : "=r"(a) : "l"(p));
    return a;
}
__device__ __forceinline__ uint32_t f2tf32(float f) {
    uint32_t r;
    asm("cvt.rna.tf32.f32 %0, %1;" : "=r"(r) : "f"(f));
    return r;
}
__device__ __forceinline__ void mma_tf32(float* c, const uint32_t* a, const uint32_t* b) {
    asm volatile(
        "mma.sync.aligned.m16n8k8.row.col.f32.tf32.tf32.f32 "
        "{%0,%1,%2,%3}, {%4,%5,%6,%7}, {%8,%9}, {%0,%1,%2,%3};"
        : "+f"(c[0]), "+f"(c[1]), "+f"(c[2]), "+f"(c[3])
        : "r"(a[0]), "r"(a[1]), "r"(a[2]), "r"(a[3]), "r"(b[0]), "r"(b[1]));
}
#define CP16(dst, src) \
    asm volatile("cp.async.cg.shared.global [%0], [%1], 16;" :: "r"(dst), "l"(src) : "memory")
#define CP_COMMIT() asm volatile("cp.async.commit_group;" ::: "memory")
#define CP_WAIT1()  asm volatile("cp.async.wait_group 1;" ::: "memory")
#define CP_WAIT0()  asm volatile("cp.async.wait_group 0;" ::: "memory")

// ---------------------------------------------------------------------------
// Kernel 1: W_eff[k][n] = sum_d (Wq[k][d]*a[d]+Wk[k][d]*b[d]+Wv[k][d]*c[d]) * Wo[d][n]
// Stored transposed (g_W[n][k]) and pre-rounded to tf32.
// ---------------------------------------------------------------------------
__global__ void build_weff_kernel(const float* __restrict__ Wq, const float* __restrict__ Wk,
                                  const float* __restrict__ Wv, const float* __restrict__ Wo,
                                  const float* __restrict__ A,  const float* __restrict__ Bm,
                                  const float* __restrict__ C) {
    __shared__ float Ms[16][17];
    __shared__ float Ws[16][17];
    const int ty = threadIdx.y, tx = threadIdx.x;
    const int row = blockIdx.y * 16 + ty;   // k index
    const int col = blockIdx.x * 16 + tx;   // n index
    float acc = 0.f;
    for (int kt = 0; kt < D_DIM; kt += 16) {
        const int k = kt + tx;
        const float a = A[k * D_DIM + k];
        const float b = Bm[k * D_DIM + k];
        const float c = C[k * D_DIM + k];
        Ms[ty][tx] = Wq[row * D_DIM + k] * a + Wk[row * D_DIM + k] * b + Wv[row * D_DIM + k] * c;
        Ws[ty][tx] = Wo[(kt + ty) * D_DIM + col];
        __syncthreads();
#pragma unroll
        for (int kk = 0; kk < 16; kk++)
            acc += Ms[ty][kk] * Ws[kk][tx];
        __syncthreads();
    }
    g_W[col * D_DIM + row] = __uint_as_float(f2tf32(acc));
}

// ---------------------------------------------------------------------------
// Kernel 2: out = x @ W_eff via tf32 mma.sync.
// BM=128, BN=112, BK=32, 3-stage cp.async pipeline, 256 threads (8 warps 4m x 2n),
// warp tile 32m x 56n -> per k8 step: 2 m16 frags, 7 n8 frags, 14 HMMA.
// ---------------------------------------------------------------------------
__global__ void __launch_bounds__(256) gemm_tf32_kernel(const float* __restrict__ x,
                                                        float* __restrict__ out) {
    extern __shared__ __align__(16) float smem[];

    const int tid   = threadIdx.x;
    const int wid   = tid >> 5;
    const int lane  = tid & 31;
    const int g     = lane >> 2;   // 0..7
    const int t     = lane & 3;    // 0..3
    const int warpM = wid & 3;     // 0..3 -> m offset 32*warpM
    const int warpN = wid >> 2;    // 0..1 -> n offset 56*warpN

    const int m0 = blockIdx.y * BM;
    const int n0 = blockIdx.x * BN;

    const uint32_t smem_base = smem_u32(smem);

    float acc[2][7][4];
#pragma unroll
    for (int i = 0; i < 2; i++)
#pragma unroll
        for (int j = 0; j < 7; j++)
#pragma unroll
            for (int q = 0; q < 4; q++) acc[i][j][q] = 0.f;

    // ---- stage loader: A tile 128x32 fp32, B tile 112x32 fp32, both padded rows
    auto load_stage = [&](int s, int kt) {
        const uint32_t aBase = smem_base + (uint32_t)(s * STG_F) * 4u;
        const uint32_t bBase = aBase + (uint32_t)AS_F * 4u;
        // A: 1024 16B chunks, 4 per thread
#pragma unroll
        for (int j = 0; j < 4; j++) {
            const int id  = tid + j * 256;
            const int row = id >> 3;
            const int c   = id & 7;
            CP16(aBase + (uint32_t)(row * A_STRIDE + c * 4) * 4u,
                 x + (size_t)(m0 + row) * D_DIM + kt + c * 4);
        }
        // B: 896 16B chunks, 3 per thread + 128 extras
#pragma unroll
        for (int j = 0; j < 3; j++) {
            const int id  = tid + j * 256;
            const int row = id >> 3;
            const int c   = id & 7;
            CP16(bBase + (uint32_t)(row * A_STRIDE + c * 4) * 4u,
                 g_W + (size_t)(n0 + row) * D_DIM + kt + c * 4);
        }
        if (tid < 128) {
            const int id  = tid + 768;
            const int row = id >> 3;
            const int c   = id & 7;
            CP16(bBase + (uint32_t)(row * A_STRIDE + c * 4) * 4u,
                 g_W + (size_t)(n0 + row) * D_DIM + kt + c * 4);
        }
    };

    // prologue: stages 0 and 1
    load_stage(0, 0);
    CP_COMMIT();
    load_stage(1, BK);
    CP_COMMIT();

    const int NIT = D_DIM / BK;   // 14
#pragma unroll 1
    for (int it = 0; it < NIT; it++) {
        CP_WAIT1();
        __syncthreads();

        // prefetch stage it+2
        if (it + 2 < NIT) load_stage((it + 2) % NSTG, (it + 2) * BK);
        CP_COMMIT();

        const float* As = smem + (it % NSTG) * STG_F;
        const float* Bs = As + AS_F;
        const float* Arow0 = As + (warpM * 32 + g) * A_STRIDE;          // mi=0 rows g
        const float* Brow  = Bs + (warpN * 56 + g) * A_STRIDE;

#pragma unroll
        for (int kk = 0; kk < 4; kk++) {
            const int k0 = kk * 8;
            uint32_t bf[7][2];
#pragma unroll
            for (int ni = 0; ni < 7; ni++) {
                bf[ni][0] = __float_as_uint(Brow[ni * 8 * A_STRIDE + k0 + t]);
                bf[ni][1] = __float_as_uint(Brow[ni * 8 * A_STRIDE + k0 + t + 4]);
            }
#pragma unroll
            for (int mi = 0; mi < 2; mi++) {
                const float* Ar = Arow0 + mi * 16 * A_STRIDE;
                uint32_t af[4];
                af[0] = f2tf32(Ar[k0 + t]);
                af[1] = f2tf32(Ar[8 * A_STRIDE + k0 + t]);
                af[2] = f2tf32(Ar[k0 + t + 4]);
                af[3] = f2tf32(Ar[8 * A_STRIDE + k0 + t + 4]);
#pragma unroll
                for (int ni = 0; ni < 7; ni++)
                    mma_tf32(acc[mi][ni], af, bf[ni]);
            }
        }
        __syncthreads();
    }
    CP_WAIT0();

    // ---- epilogue: each thread owns rows (g, g+8), cols (2t, 2t+1) per (mi, ni)
#pragma unroll
    for (int mi = 0; mi < 2; mi++) {
        const int r0 = m0 + warpM * 32 + mi * 16 + g;
#pragma unroll
        for (int ni = 0; ni < 7; ni++) {
            const int c0 = n0 + warpN * 56 + ni * 8 + 2 * t;
            float2 v0, v1;
            v0.x = acc[mi][ni][0]; v0.y = acc[mi][ni][1];
            v1.x = acc[mi][ni][2]; v1.y = acc[mi][ni][3];
            *reinterpret_cast<float2*>(out + (size_t)r0 * D_DIM + c0)       = v0;
            *reinterpret_cast<float2*>(out + (size_t)(r0 + 8) * D_DIM + c0) = v1;
        }
    }
}

// ---------------------------------------------------------------------------
extern "C" void kernel_launch(void* const* d_in, const int* in_sizes, int n_in,
                              void* d_out, int out_size) {
    const float* x  = (const float*)d_in[0];
    const float* Wq = (const float*)d_in[1];
    const float* Wk = (const float*)d_in[2];
    const float* Wv = (const float*)d_in[3];
    const float* Wo = (const float*)d_in[4];
    const float* A  = (const float*)d_in[5];
    const float* B  = (const float*)d_in[6];
    const float* C  = (const float*)d_in[7];

    cudaFuncSetAttribute(gemm_tf32_kernel, cudaFuncAttributeMaxDynamicSharedMemorySize,
                         SMEM_BYTES);

    build_weff_kernel<<<dim3(D_DIM / 16, D_DIM / 16), dim3(16, 16)>>>(Wq, Wk, Wv, Wo, A, B, C);
    gemm_tf32_kernel<<<dim3(D_DIM / BN, MTOT / BM), 256, SMEM_BYTES>>>(x, (float*)d_out);
}